// round 1
// baseline (speedup 1.0000x reference)
#include <cuda_runtime.h>
#include <cuda_bf16.h>
#include <math.h>

// Problem constants (fixed by setup_inputs)
#define B_ROWS   4096
#define T_LEN    3600
#define K_FOLD   900      // folded K (period 1800, +/- fold at 900)
#define K_PAD    928      // 29 * 32
#define N_PAD    512      // even group cols [0,256), odd group cols [256,512)
#define N_GRID   201
#define FMIN     40
#define DELTA    5

// Static device scratch (no allocations allowed)
__device__ float  g_Yt[2][(size_t)K_PAD * B_ROWS];   // [parity][t][b], ~30.4 MB
__device__ float  g_basisT[(size_t)K_PAD * N_PAD];   // [t][n], ~1.9 MB
__device__ float  g_C[(size_t)B_ROWS * N_PAD];       // GEMM output, ~8.4 MB
__device__ double g_acc;

// ---------------------------------------------------------------------------
__global__ void init_kernel() { g_acc = 0.0; }

// Basis: column mapping
//   even group (cols 0..255):  cos at col ge (g=40+2ge, ge<101), sin at col 101+ge; 202..255 zero
//   odd  group (cols 256..511): cos at col 256+go (g=41+2go, go<100), sin at col 356+go; 456..511 zero
__global__ void basis_kernel() {
    int idx = blockIdx.x * 256 + threadIdx.x;
    if (idx >= K_PAD * N_PAD) return;
    int t = idx >> 9;        // / 512
    int n = idx & (N_PAD - 1);
    float v = 0.0f;
    if (t < K_FOLD) {
        int grp = n >> 8;
        int w   = n & 255;
        int g = -1, comp = 0;
        if (grp == 0) {
            if (w < 101)      { g = 40 + 2 * w;         comp = 0; }
            else if (w < 202) { g = 40 + 2 * (w - 101); comp = 1; }
        } else {
            if (w < 100)      { g = 41 + 2 * w;         comp = 0; }
            else if (w < 200) { g = 41 + 2 * (w - 100); comp = 1; }
        }
        if (g >= 0) {
            int r = (g * t) % 1800;   // exact integer phase reduction
            float ang = (float)((double)r * (6.283185307179586476925287 / 1800.0));
            v = comp ? sinf(ang) : cosf(ang);
        }
    }
    g_basisT[idx] = v;
}

// Fold + transpose: x[b][t] -> Yt[p][t][b] (t-major so the GEMM loads coalesced)
__global__ void fold_kernel(const float* __restrict__ x) {
    __shared__ float se[32][33];
    __shared__ float so[32][33];
    int b0 = blockIdx.x * 32;
    int t0 = blockIdx.y * 32;
    int tx = threadIdx.x;   // 0..31
    int ty = threadIdx.y;   // 0..7
    #pragma unroll
    for (int i = 0; i < 32; i += 8) {
        int b = b0 + ty + i;
        int t = t0 + tx;
        float ye = 0.0f, yo = 0.0f;
        if (t < K_FOLD) {
            const float* xr = x + (size_t)b * T_LEN;
            float x0 = xr[t], x1 = xr[t + 900], x2 = xr[t + 1800], x3 = xr[t + 2700];
            float s02 = x0 + x2, s13 = x1 + x3;
            ye = s02 + s13;
            yo = s02 - s13;
        }
        se[ty + i][tx] = ye;
        so[ty + i][tx] = yo;
    }
    __syncthreads();
    #pragma unroll
    for (int i = 0; i < 32; i += 8) {
        int t = t0 + ty + i;
        int b = b0 + tx;
        size_t o = (size_t)t * B_ROWS + b;
        g_Yt[0][o] = se[tx][ty + i];
        g_Yt[1][o] = so[tx][ty + i];
    }
}

// SGEMM: C[4096][512] = Yt[p]^T (M=4096 x K=928) * basisT (K x N=512)
// Tiles: BM=128, BN=128, BK=32; 256 threads, 8x8 micro-tile.
// grid = (32, 4); n-tiles 0..1 -> even parity, 2..3 -> odd.
__global__ void __launch_bounds__(256) gemm_kernel() {
    __shared__ float Ys[32][128];
    __shared__ float Bs[32][128];

    int m0    = blockIdx.x * 128;
    int ntile = blockIdx.y;           // 0..3
    int p     = ntile >> 1;           // parity select of Y
    int n0    = ntile * 128;

    const float* __restrict__ Yb = g_Yt[p];

    int tid = threadIdx.x;
    int tm  = tid & 15;   // m micro position
    int tn  = tid >> 4;   // n micro position
    int lk  = tid >> 5;   // 0..7  (k row for loads)
    int lq  = tid & 31;   // 0..31 (float4 index for loads)

    float acc[8][8];
    #pragma unroll
    for (int i = 0; i < 8; i++)
        #pragma unroll
        for (int j = 0; j < 8; j++) acc[i][j] = 0.0f;

    for (int k0 = 0; k0 < K_PAD; k0 += 32) {
        __syncthreads();
        #pragma unroll
        for (int i = 0; i < 4; i++) {
            int k = lk + i * 8;
            *(float4*)&Ys[k][lq * 4] =
                *(const float4*)&Yb[(size_t)(k0 + k) * B_ROWS + m0 + lq * 4];
            *(float4*)&Bs[k][lq * 4] =
                *(const float4*)&g_basisT[(size_t)(k0 + k) * N_PAD + n0 + lq * 4];
        }
        __syncthreads();
        #pragma unroll
        for (int k = 0; k < 32; k++) {
            float4 a0 = *(float4*)&Ys[k][tm * 4];
            float4 a1 = *(float4*)&Ys[k][tm * 4 + 64];
            float4 b0 = *(float4*)&Bs[k][tn * 4];
            float4 b1 = *(float4*)&Bs[k][tn * 4 + 64];
            float av[8] = {a0.x, a0.y, a0.z, a0.w, a1.x, a1.y, a1.z, a1.w};
            float bv[8] = {b0.x, b0.y, b0.z, b0.w, b1.x, b1.y, b1.z, b1.w};
            #pragma unroll
            for (int i = 0; i < 8; i++)
                #pragma unroll
                for (int j = 0; j < 8; j++)
                    acc[i][j] = fmaf(av[i], bv[j], acc[i][j]);
        }
    }

    #pragma unroll
    for (int i = 0; i < 8; i++) {
        int m = m0 + tm * 4 + (i & 3) + ((i >> 2) * 64);
        #pragma unroll
        for (int j = 0; j < 8; j++) {
            int n = n0 + tn * 4 + (j & 3) + ((j >> 2) * 64);
            g_C[(size_t)m * N_PAD + n] = acc[i][j];
        }
    }
}

// Per-row SNR, accumulate into double
__global__ void reduce_kernel(const int* __restrict__ f_true) {
    int b   = blockIdx.x;
    int tid = threadIdx.x;  // 256
    const float* Cr = g_C + (size_t)b * N_PAD;
    float w = 0.0f, u = 0.0f;
    if (tid < N_GRID) {
        int g = FMIN + tid;
        int ccol, scol;
        if ((g & 1) == 0) { int ge = tid >> 1; ccol = ge;       scol = 101 + ge; }
        else              { int go = tid >> 1; ccol = 256 + go; scol = 356 + go; }
        float a = Cr[ccol];
        float s = Cr[scol];
        float psd = a * a + s * s;
        int d = g - f_true[b];
        if (d < 0) d = -d;
        if (d <= DELTA) w = psd; else u = psd;
    }
    __shared__ float sw[256];
    __shared__ float su[256];
    sw[tid] = w; su[tid] = u;
    __syncthreads();
    for (int off = 128; off > 0; off >>= 1) {
        if (tid < off) { sw[tid] += sw[tid + off]; su[tid] += su[tid + off]; }
        __syncthreads();
    }
    if (tid == 0) {
        float snr = 10.0f * log10f((sw[0] * 190.0f) / (su[0] * 11.0f));
        atomicAdd(&g_acc, (double)snr);
    }
}

__global__ void finalize_kernel(float* out) {
    out[0] = (float)(-g_acc * (1.0 / 4096.0));
}

// ---------------------------------------------------------------------------
extern "C" void kernel_launch(void* const* d_in, const int* in_sizes, int n_in,
                              void* d_out, int out_size) {
    const float* x      = (const float*)d_in[0];
    const int*   f_true = (const int*)d_in[1];
    float*       out    = (float*)d_out;

    init_kernel<<<1, 1>>>();
    basis_kernel<<<(K_PAD * N_PAD + 255) / 256, 256>>>();
    fold_kernel<<<dim3(B_ROWS / 32, K_PAD / 32), dim3(32, 8)>>>(x);
    gemm_kernel<<<dim3(B_ROWS / 128, N_PAD / 128), 256>>>();
    reduce_kernel<<<B_ROWS, 256>>>(f_true);
    finalize_kernel<<<1, 1>>>(out);
}